// round 4
// baseline (speedup 1.0000x reference)
#include <cuda_runtime.h>
#include <cuda_bf16.h>
#include <cmath>

#define T_  200
#define B_  256
#define M_  (T_ * B_)      // 51200 rows

__device__ float g_xproj[M_ * 200];  // [T,B,4H] flat row r = t*256+b

// ---------------- f32x2 packed fp32 helpers ----------------
__device__ __forceinline__ unsigned long long fma2(unsigned long long a,
                                                   unsigned long long b,
                                                   unsigned long long c) {
    unsigned long long d;
    asm("fma.rn.f32x2 %0, %1, %2, %3;" : "=l"(d) : "l"(a), "l"(b), "l"(c));
    return d;
}
__device__ __forceinline__ float2 u2f(unsigned long long v) {
    float2 r;
    asm("mov.b64 {%0, %1}, %2;" : "=f"(r.x), "=f"(r.y) : "l"(v));
    return r;
}
__device__ __forceinline__ unsigned smem_u32(const void* p) {
    return (unsigned)__cvta_generic_to_shared(p);
}
__device__ __forceinline__ void cp16(unsigned dst, const void* src) {
    asm volatile("cp.async.cg.shared.global [%0], [%1], 16;" :: "r"(dst), "l"(src));
}
__device__ __forceinline__ float frcp(float x) {
    float r; asm("rcp.approx.f32 %0, %1;" : "=f"(r) : "f"(x)); return r;
}
__device__ __forceinline__ float sigm(float x) {
    return frcp(1.f + __expf(-x));
}

// ---------------------------------------------------------------------------
// K1: x_proj = gather(emb, tokens) @ Wih^T + (bih+bhh)   (unchanged from R3)
// ---------------------------------------------------------------------------
#define K1_ASZ  8192                 // 64 rows * 128 floats
#define K1_BSZ  25600
#define K1_SMEM_WORDS (K1_BSZ + 2*K1_ASZ + 200)

__global__ __launch_bounds__(512, 1) void k1_xproj(
    const int*   __restrict__ tokens,
    const float* __restrict__ emb,
    const float* __restrict__ Wih,
    const float* __restrict__ bih,
    const float* __restrict__ bhh)
{
    extern __shared__ __align__(16) float sm[];
    float* Bs   = sm;
    float* As   = sm + K1_BSZ;
    float* bsum = sm + K1_BSZ + 2*K1_ASZ;

    const int tid  = threadIdx.x;
    const int lane = tid & 31;
    const int warp = tid >> 5;
    const int cgB  = (warp >= 8);
    const int rg   = warp & 7;

    for (int i = tid; i < K1_BSZ; i += 512) {
        const int n = i >> 7;
        const int k = i & 127;
        Bs[(k >> 1) * 400 + 2 * n + (k & 1)] = Wih[i];
    }
    if (tid < 200) bsum[tid] = bih[tid] + bhh[tid];

    const int cta   = blockIdx.x;
    const int nblk  = (cta < 60) ? 6 : 5;
    const int start = cta * 5 + ((cta < 60) ? cta : 60);

    {
        const int row0 = start * 64;
        for (int i = tid; i < 2048; i += 512) {
            const int m  = i >> 5;
            const int ch = i & 31;
            cp16(smem_u32(&As[m * 128 + ch * 4]),
                 emb + (size_t)tokens[row0 + m] * 128 + ch * 4);
        }
        asm volatile("cp.async.commit_group;");
    }

    for (int blk = 0; blk < nblk; blk++) {
        asm volatile("cp.async.wait_group 0;");
        __syncthreads();

        if (blk + 1 < nblk) {
            const int row0 = (start + blk + 1) * 64;
            float* dst = As + ((blk + 1) & 1) * K1_ASZ;
            for (int i = tid; i < 2048; i += 512) {
                const int m  = i >> 5;
                const int ch = i & 31;
                cp16(smem_u32(&dst[m * 128 + ch * 4]),
                     emb + (size_t)tokens[row0 + m] * 128 + ch * 4);
            }
            asm volatile("cp.async.commit_group;");
        }

        const float* Ab = As + (blk & 1) * K1_ASZ + rg * 8 * 128;
        const int wbase = cgB ? (256 + 4 * lane) : (8 * lane);

        unsigned long long acc[8][4];
#pragma unroll
        for (int m = 0; m < 8; m++)
#pragma unroll
            for (int j = 0; j < 4; j++) acc[m][j] = 0ull;

#pragma unroll 2
        for (int kk4 = 0; kk4 < 32; kk4++) {
            const float* brow = &Bs[kk4 * 800];
            ulonglong2 p0, p1, p2, p3;
            if (!cgB) {
                p0 = *reinterpret_cast<const ulonglong2*>(brow + wbase);
                p1 = *reinterpret_cast<const ulonglong2*>(brow + wbase + 4);
                p2 = *reinterpret_cast<const ulonglong2*>(brow + wbase + 400);
                p3 = *reinterpret_cast<const ulonglong2*>(brow + wbase + 404);
            } else {
                p0 = *reinterpret_cast<const ulonglong2*>(brow + wbase);
                p2 = *reinterpret_cast<const ulonglong2*>(brow + wbase + 400);
                if (lane < 4) {
                    p1 = *reinterpret_cast<const ulonglong2*>(brow + 384 + 4*lane);
                    p3 = *reinterpret_cast<const ulonglong2*>(brow + 784 + 4*lane);
                } else { p1 = make_ulonglong2(0,0); p3 = make_ulonglong2(0,0); }
            }
#pragma unroll
            for (int m = 0; m < 8; m++) {
                const ulonglong2 av = *reinterpret_cast<const ulonglong2*>(
                    &Ab[m * 128 + kk4 * 4]);
                acc[m][0] = fma2(av.x, p0.x, acc[m][0]);
                acc[m][1] = fma2(av.x, p0.y, acc[m][1]);
                acc[m][2] = fma2(av.x, p1.x, acc[m][2]);
                acc[m][3] = fma2(av.x, p1.y, acc[m][3]);
                acc[m][0] = fma2(av.y, p2.x, acc[m][0]);
                acc[m][1] = fma2(av.y, p2.y, acc[m][1]);
                acc[m][2] = fma2(av.y, p3.x, acc[m][2]);
                acc[m][3] = fma2(av.y, p3.y, acc[m][3]);
            }
        }

        const int r0 = (start + blk) * 64 + rg * 8;
        if (!cgB) {
            const float4 bq = *reinterpret_cast<const float4*>(&bsum[4 * lane]);
#pragma unroll
            for (int m = 0; m < 8; m++) {
                const float2 s0 = u2f(acc[m][0]), s1 = u2f(acc[m][1]);
                const float2 s2 = u2f(acc[m][2]), s3 = u2f(acc[m][3]);
                float4 o;
                o.x = s0.x + s0.y + bq.x;
                o.y = s1.x + s1.y + bq.y;
                o.z = s2.x + s2.y + bq.z;
                o.w = s3.x + s3.y + bq.w;
                *reinterpret_cast<float4*>(
                    &g_xproj[(size_t)(r0 + m) * 200 + 4 * lane]) = o;
            }
        } else {
#pragma unroll
            for (int m = 0; m < 8; m++) {
                const float2 s0 = u2f(acc[m][0]), s1 = u2f(acc[m][1]);
                float2 o;
                o.x = s0.x + s0.y + bsum[128 + 2 * lane];
                o.y = s1.x + s1.y + bsum[129 + 2 * lane];
                *reinterpret_cast<float2*>(
                    &g_xproj[(size_t)(r0 + m) * 200 + 128 + 2 * lane]) = o;
                if (lane < 4) {
                    const float2 s2 = u2f(acc[m][2]), s3 = u2f(acc[m][3]);
                    float2 o2;
                    o2.x = s2.x + s2.y + bsum[192 + 2 * lane];
                    o2.y = s3.x + s3.y + bsum[193 + 2 * lane];
                    *reinterpret_cast<float2*>(
                        &g_xproj[(size_t)(r0 + m) * 200 + 192 + 2 * lane]) = o2;
                }
            }
        }
        __syncthreads();
    }
}

// ---------------------------------------------------------------------------
// K2: LSTM recurrence + fused MLP head.
// 128 CTAs x 512 threads, 2 groups of 256; group g owns batch b = blk*2+g.
// Roles: n<200 gates (n<50 also cell update + cp.async loader);
//        n in [224,240) head-z (warp 7, no divergence with gates);
//        n in [240,249) head-out.
// x_proj staged through an 8-deep cp.async smem ring: at iter t, loader thread
// j issues stage t+7 into slot (t-1)%8 (freed slot), wait_group 5 guarantees
// stage t+2 complete before the phase-1 barrier -> ~6-step prefetch distance.
// ---------------------------------------------------------------------------
#define S_ 8

__global__ __launch_bounds__(512, 1) void k2_lstm(
    const float* __restrict__ Whh,
    const float* __restrict__ W1, const float* __restrict__ b1,
    const float* __restrict__ W2, const float* __restrict__ b2,
    float* __restrict__ out)
{
    __shared__ __align__(16) float h_s[2][52];
    __shared__ float gates_s[2][200];
    __shared__ __align__(16) float z_s[2][16];
    __shared__ __align__(16) float xs[2][S_][200];

    const int tid = threadIdx.x;
    const int g   = tid >> 8;
    const int n   = tid & 255;
    const int b   = blockIdx.x * 2 + g;

    const bool gate   = (n < 200);
    const bool loader = (n < 50);
    const bool zrole  = (n >= 224 && n < 240);
    const bool orole  = (n >= 240 && n < 249);

    unsigned long long w2[25];
    float bias = 0.f;
    if (gate) {
        const float2* wr = reinterpret_cast<const float2*>(Whh + n * 50);
#pragma unroll
        for (int q = 0; q < 25; q++)
            w2[q] = *reinterpret_cast<const unsigned long long*>(&wr[q]);
    } else if (zrole) {
        const int j = n - 224;
        const float2* wr = reinterpret_cast<const float2*>(W1 + j * 50);
#pragma unroll
        for (int q = 0; q < 25; q++)
            w2[q] = *reinterpret_cast<const unsigned long long*>(&wr[q]);
        bias = b1[j];
    } else if (orole) {
        const int p = n - 240;
        const float2* wr = reinterpret_cast<const float2*>(W2 + p * 16);
#pragma unroll
        for (int q = 0; q < 8; q++)
            w2[q] = *reinterpret_cast<const unsigned long long*>(&wr[q]);
        bias = b2[p];
    }
    if (n < 52) h_s[g][n] = 0.f;

    // Prologue: stage x_proj for steps 0..S_-2
    if (loader) {
#pragma unroll
        for (int s = 0; s < S_ - 1; s++) {
            cp16(smem_u32(&xs[g][s][n * 4]),
                 g_xproj + ((size_t)(s * B_ + b) * 200) + n * 4);
            asm volatile("cp.async.commit_group;");
        }
        asm volatile("cp.async.wait_group %0;" :: "n"(S_ - 3));
    }
    __syncthreads();

    float c = 0.f;

    for (int t = 0; t < T_; t++) {
        const int slot = t & (S_ - 1);

        // issue prefetch for stage t+S_-1 into the slot freed at t-1
        if (loader) {
            const int ts = t + S_ - 1;
            if (ts < T_)
                cp16(smem_u32(&xs[g][(ts) & (S_ - 1)][n * 4]),
                     g_xproj + ((size_t)(ts * B_ + b) * 200) + n * 4);
            asm volatile("cp.async.commit_group;");
        }

        // ---- phase 1: gates(t) + head-z(t-1) ----
        if (gate) {
            const float xp = xs[g][slot][n];
            const unsigned long long* h2 =
                reinterpret_cast<const unsigned long long*>(h_s[g]);
            unsigned long long a0 = 0ull, a1 = 0ull, a2 = 0ull, a3 = 0ull;
#pragma unroll
            for (int q = 0; q < 24; q += 4) {
                a0 = fma2(h2[q],     w2[q],     a0);
                a1 = fma2(h2[q + 1], w2[q + 1], a1);
                a2 = fma2(h2[q + 2], w2[q + 2], a2);
                a3 = fma2(h2[q + 3], w2[q + 3], a3);
            }
            a0 = fma2(h2[24], w2[24], a0);
            const float2 s0 = u2f(a0), s1 = u2f(a1), s2 = u2f(a2), s3 = u2f(a3);
            gates_s[g][n] = xp + ((s0.x + s0.y) + (s1.x + s1.y))
                               + ((s2.x + s2.y) + (s3.x + s3.y));
        } else if (zrole && t > 0) {
            const unsigned long long* h2 =
                reinterpret_cast<const unsigned long long*>(h_s[g]);
            unsigned long long a0 = 0ull, a1 = 0ull;
#pragma unroll
            for (int q = 0; q < 24; q += 2) {
                a0 = fma2(h2[q],     w2[q],     a0);
                a1 = fma2(h2[q + 1], w2[q + 1], a1);
            }
            a0 = fma2(h2[24], w2[24], a0);
            const float2 s0 = u2f(a0), s1 = u2f(a1);
            z_s[g][n - 224] = fmaxf(bias + (s0.x + s0.y) + (s1.x + s1.y), 0.f);
        }
        if (loader)
            asm volatile("cp.async.wait_group %0;" :: "n"(S_ - 3));
        asm volatile("bar.sync %0, 256;" :: "r"(g + 1) : "memory");

        // ---- phase 2: cell update(t) + head-out(t-1) ----
        if (n < 50) {
            const float iv = gates_s[g][n];
            const float fv = gates_s[g][n + 50];
            const float gv = gates_s[g][n + 100];
            const float ov = gates_s[g][n + 150];
            const float si = sigm(iv);
            const float sf = sigm(fv);
            const float so = sigm(ov);
            const float tg = fmaf(2.f, sigm(2.f * gv), -1.f);
            c = fmaf(sf, c, si * tg);
            const float tc = fmaf(2.f, sigm(2.f * c), -1.f);
            h_s[g][n] = so * tc;
        } else if (orole && t > 0) {
            const unsigned long long* z2 =
                reinterpret_cast<const unsigned long long*>(z_s[g]);
            unsigned long long a0 = 0ull, a1 = 0ull;
#pragma unroll
            for (int q = 0; q < 8; q += 2) {
                a0 = fma2(z2[q],     w2[q],     a0);
                a1 = fma2(z2[q + 1], w2[q + 1], a1);
            }
            const float2 s0 = u2f(a0), s1 = u2f(a1);
            out[(size_t)((t - 1) * B_ + b) * 9 + (n - 240)] =
                bias + (s0.x + s0.y) + (s1.x + s1.y);
        }
        asm volatile("bar.sync %0, 256;" :: "r"(g + 1) : "memory");
    }

    // ---- epilogue: head for t = 199 ----
    if (zrole) {
        const unsigned long long* h2 =
            reinterpret_cast<const unsigned long long*>(h_s[g]);
        unsigned long long a0 = 0ull, a1 = 0ull;
#pragma unroll
        for (int q = 0; q < 24; q += 2) {
            a0 = fma2(h2[q],     w2[q],     a0);
            a1 = fma2(h2[q + 1], w2[q + 1], a1);
        }
        a0 = fma2(h2[24], w2[24], a0);
        const float2 s0 = u2f(a0), s1 = u2f(a1);
        z_s[g][n - 224] = fmaxf(bias + (s0.x + s0.y) + (s1.x + s1.y), 0.f);
    }
    asm volatile("bar.sync %0, 256;" :: "r"(g + 1) : "memory");
    if (orole) {
        const unsigned long long* z2 =
            reinterpret_cast<const unsigned long long*>(z_s[g]);
        unsigned long long a0 = 0ull, a1 = 0ull;
#pragma unroll
        for (int q = 0; q < 8; q += 2) {
            a0 = fma2(z2[q],     w2[q],     a0);
            a1 = fma2(z2[q + 1], w2[q + 1], a1);
        }
        const float2 s0 = u2f(a0), s1 = u2f(a1);
        out[(size_t)(199 * B_ + b) * 9 + (n - 240)] =
            bias + (s0.x + s0.y) + (s1.x + s1.y);
    }
}

// ---------------------------------------------------------------------------
extern "C" void kernel_launch(void* const* d_in, const int* in_sizes, int n_in,
                              void* d_out, int out_size)
{
    const int*   tokens = (const int*)  d_in[0];
    const float* emb    = (const float*)d_in[1];
    const float* Wih    = (const float*)d_in[2];
    const float* Whh    = (const float*)d_in[3];
    const float* bih    = (const float*)d_in[4];
    const float* bhh    = (const float*)d_in[5];
    const float* W1     = (const float*)d_in[6];
    const float* b1     = (const float*)d_in[7];
    const float* W2     = (const float*)d_in[8];
    const float* b2     = (const float*)d_in[9];
    float* out = (float*)d_out;

    const int k1_smem = K1_SMEM_WORDS * 4;   // 168,736 B
    cudaFuncSetAttribute(k1_xproj, cudaFuncAttributeMaxDynamicSharedMemorySize,
                         k1_smem);

    k1_xproj<<<148, 512, k1_smem>>>(tokens, emb, Wih, bih, bhh);
    k2_lstm <<<B_ / 2, 512>>>(Whh, W1, b1, W2, b2, out);
}

// round 5
// speedup vs baseline: 1.1149x; 1.1149x over previous
#include <cuda_runtime.h>
#include <cuda_bf16.h>
#include <cmath>

#define T_  200
#define B_  256
#define M_  (T_ * B_)      // 51200 rows

__device__ float g_xproj[M_ * 200];  // [T,B,4H] flat row r = t*256+b
__device__ float g_hs[M_ * 50];      // [T,B,H]

// ---------------- f32x2 packed fp32 helpers ----------------
__device__ __forceinline__ unsigned long long fma2(unsigned long long a,
                                                   unsigned long long b,
                                                   unsigned long long c) {
    unsigned long long d;
    asm("fma.rn.f32x2 %0, %1, %2, %3;" : "=l"(d) : "l"(a), "l"(b), "l"(c));
    return d;
}
__device__ __forceinline__ unsigned long long add2(unsigned long long a,
                                                   unsigned long long b) {
    unsigned long long d;
    asm("add.rn.f32x2 %0, %1, %2;" : "=l"(d) : "l"(a), "l"(b));
    return d;
}
__device__ __forceinline__ float2 u2f(unsigned long long v) {
    float2 r;
    asm("mov.b64 {%0, %1}, %2;" : "=f"(r.x), "=f"(r.y) : "l"(v));
    return r;
}
__device__ __forceinline__ unsigned smem_u32(const void* p) {
    return (unsigned)__cvta_generic_to_shared(p);
}
__device__ __forceinline__ void cp16(unsigned dst, const void* src) {
    asm volatile("cp.async.cg.shared.global [%0], [%1], 16;" :: "r"(dst), "l"(src));
}
__device__ __forceinline__ float frcp(float x) {
    float r; asm("rcp.approx.f32 %0, %1;" : "=f"(r) : "f"(x)); return r;
}
__device__ __forceinline__ float sigm(float x) {
    return frcp(1.f + __expf(-x));
}

// ---------------------------------------------------------------------------
// K1: x_proj = gather(emb, tokens) @ Wih^T + (bih+bhh)   (unchanged)
// ---------------------------------------------------------------------------
#define K1_ASZ  8192
#define K1_BSZ  25600
#define K1_SMEM_WORDS (K1_BSZ + 2*K1_ASZ + 200)

__global__ __launch_bounds__(512, 1) void k1_xproj(
    const int*   __restrict__ tokens,
    const float* __restrict__ emb,
    const float* __restrict__ Wih,
    const float* __restrict__ bih,
    const float* __restrict__ bhh)
{
    extern __shared__ __align__(16) float sm[];
    float* Bs   = sm;
    float* As   = sm + K1_BSZ;
    float* bsum = sm + K1_BSZ + 2*K1_ASZ;

    const int tid  = threadIdx.x;
    const int lane = tid & 31;
    const int warp = tid >> 5;
    const int cgB  = (warp >= 8);
    const int rg   = warp & 7;

    for (int i = tid; i < K1_BSZ; i += 512) {
        const int n = i >> 7;
        const int k = i & 127;
        Bs[(k >> 1) * 400 + 2 * n + (k & 1)] = Wih[i];
    }
    if (tid < 200) bsum[tid] = bih[tid] + bhh[tid];

    const int cta   = blockIdx.x;
    const int nblk  = (cta < 60) ? 6 : 5;
    const int start = cta * 5 + ((cta < 60) ? cta : 60);

    {
        const int row0 = start * 64;
        for (int i = tid; i < 2048; i += 512) {
            const int m  = i >> 5;
            const int ch = i & 31;
            cp16(smem_u32(&As[m * 128 + ch * 4]),
                 emb + (size_t)tokens[row0 + m] * 128 + ch * 4);
        }
        asm volatile("cp.async.commit_group;");
    }

    for (int blk = 0; blk < nblk; blk++) {
        asm volatile("cp.async.wait_group 0;");
        __syncthreads();

        if (blk + 1 < nblk) {
            const int row0 = (start + blk + 1) * 64;
            float* dst = As + ((blk + 1) & 1) * K1_ASZ;
            for (int i = tid; i < 2048; i += 512) {
                const int m  = i >> 5;
                const int ch = i & 31;
                cp16(smem_u32(&dst[m * 128 + ch * 4]),
                     emb + (size_t)tokens[row0 + m] * 128 + ch * 4);
            }
            asm volatile("cp.async.commit_group;");
        }

        const float* Ab = As + (blk & 1) * K1_ASZ + rg * 8 * 128;
        const int wbase = cgB ? (256 + 4 * lane) : (8 * lane);

        unsigned long long acc[8][4];
#pragma unroll
        for (int m = 0; m < 8; m++)
#pragma unroll
            for (int j = 0; j < 4; j++) acc[m][j] = 0ull;

#pragma unroll 2
        for (int kk4 = 0; kk4 < 32; kk4++) {
            const float* brow = &Bs[kk4 * 800];
            ulonglong2 p0, p1, p2, p3;
            if (!cgB) {
                p0 = *reinterpret_cast<const ulonglong2*>(brow + wbase);
                p1 = *reinterpret_cast<const ulonglong2*>(brow + wbase + 4);
                p2 = *reinterpret_cast<const ulonglong2*>(brow + wbase + 400);
                p3 = *reinterpret_cast<const ulonglong2*>(brow + wbase + 404);
            } else {
                p0 = *reinterpret_cast<const ulonglong2*>(brow + wbase);
                p2 = *reinterpret_cast<const ulonglong2*>(brow + wbase + 400);
                if (lane < 4) {
                    p1 = *reinterpret_cast<const ulonglong2*>(brow + 384 + 4*lane);
                    p3 = *reinterpret_cast<const ulonglong2*>(brow + 784 + 4*lane);
                } else { p1 = make_ulonglong2(0,0); p3 = make_ulonglong2(0,0); }
            }
#pragma unroll
            for (int m = 0; m < 8; m++) {
                const ulonglong2 av = *reinterpret_cast<const ulonglong2*>(
                    &Ab[m * 128 + kk4 * 4]);
                acc[m][0] = fma2(av.x, p0.x, acc[m][0]);
                acc[m][1] = fma2(av.x, p0.y, acc[m][1]);
                acc[m][2] = fma2(av.x, p1.x, acc[m][2]);
                acc[m][3] = fma2(av.x, p1.y, acc[m][3]);
                acc[m][0] = fma2(av.y, p2.x, acc[m][0]);
                acc[m][1] = fma2(av.y, p2.y, acc[m][1]);
                acc[m][2] = fma2(av.y, p3.x, acc[m][2]);
                acc[m][3] = fma2(av.y, p3.y, acc[m][3]);
            }
        }

        const int r0 = (start + blk) * 64 + rg * 8;
        if (!cgB) {
            const float4 bq = *reinterpret_cast<const float4*>(&bsum[4 * lane]);
#pragma unroll
            for (int m = 0; m < 8; m++) {
                const float2 s0 = u2f(acc[m][0]), s1 = u2f(acc[m][1]);
                const float2 s2 = u2f(acc[m][2]), s3 = u2f(acc[m][3]);
                float4 o;
                o.x = s0.x + s0.y + bq.x;
                o.y = s1.x + s1.y + bq.y;
                o.z = s2.x + s2.y + bq.z;
                o.w = s3.x + s3.y + bq.w;
                *reinterpret_cast<float4*>(
                    &g_xproj[(size_t)(r0 + m) * 200 + 4 * lane]) = o;
            }
        } else {
#pragma unroll
            for (int m = 0; m < 8; m++) {
                const float2 s0 = u2f(acc[m][0]), s1 = u2f(acc[m][1]);
                float2 o;
                o.x = s0.x + s0.y + bsum[128 + 2 * lane];
                o.y = s1.x + s1.y + bsum[129 + 2 * lane];
                *reinterpret_cast<float2*>(
                    &g_xproj[(size_t)(r0 + m) * 200 + 128 + 2 * lane]) = o;
                if (lane < 4) {
                    const float2 s2 = u2f(acc[m][2]), s3 = u2f(acc[m][3]);
                    float2 o2;
                    o2.x = s2.x + s2.y + bsum[192 + 2 * lane];
                    o2.y = s3.x + s3.y + bsum[193 + 2 * lane];
                    *reinterpret_cast<float2*>(
                        &g_xproj[(size_t)(r0 + m) * 200 + 192 + 2 * lane]) = o2;
                }
            }
        }
        __syncthreads();
    }
}

// ---------------------------------------------------------------------------
// K2: LSTM recurrence only (head un-fused). 128 CTAs x 512 threads, 2 groups.
// Role index v: group 0 -> v = n; group 1 -> v = (n+64)&255, so group 1's
// cell/loader warps are warps 10-11 (SMSP 2,3) while group 0's are warps 0-1
// (SMSP 0,1): every SMSP gets exactly one cell warp -> phase-2 MUFU issue and
// latency hiding spread across all 4 schedulers.
// x_proj staged through an 8-deep cp.async smem ring (as R4).
// ---------------------------------------------------------------------------
#define S_ 8

__global__ __launch_bounds__(512, 1) void k2_lstm(const float* __restrict__ Whh)
{
    __shared__ __align__(16) float h_s[2][52];
    __shared__ float gates_s[2][200];
    __shared__ __align__(16) float xs[2][S_][200];

    const int tid = threadIdx.x;
    const int g   = tid >> 8;
    const int n   = tid & 255;
    const int v   = g ? ((n + 64) & 255) : n;   // rotated role index
    const int b   = blockIdx.x * 2 + g;

    const bool gate   = (v < 200);
    const bool loader = (v < 50);

    unsigned long long w2[25];
    if (gate) {
        const float2* wr = reinterpret_cast<const float2*>(Whh + v * 50);
#pragma unroll
        for (int q = 0; q < 25; q++)
            w2[q] = *reinterpret_cast<const unsigned long long*>(&wr[q]);
    }
    if (v < 52) h_s[g][v] = 0.f;

    // Prologue: stage x_proj for steps 0..S_-2
    if (loader) {
#pragma unroll
        for (int s = 0; s < S_ - 1; s++) {
            cp16(smem_u32(&xs[g][s][v * 4]),
                 g_xproj + ((size_t)(s * B_ + b) * 200) + v * 4);
            asm volatile("cp.async.commit_group;");
        }
        asm volatile("cp.async.wait_group %0;" :: "n"(S_ - 3));
    }
    __syncthreads();

    float c = 0.f;

    for (int t = 0; t < T_; t++) {
        const int slot = t & (S_ - 1);

        // issue prefetch for stage t+S_-1 into the slot freed at t-1
        if (loader) {
            const int ts = t + S_ - 1;
            if (ts < T_)
                cp16(smem_u32(&xs[g][ts & (S_ - 1)][v * 4]),
                     g_xproj + ((size_t)(ts * B_ + b) * 200) + v * 4);
            asm volatile("cp.async.commit_group;");
        }

        // ---- phase 1: gates(t) ----
        if (gate) {
            const float xp = xs[g][slot][v];
            const unsigned long long* h2 =
                reinterpret_cast<const unsigned long long*>(h_s[g]);
            unsigned long long a0 = 0ull, a1 = 0ull, a2 = 0ull, a3 = 0ull;
#pragma unroll
            for (int q = 0; q < 24; q += 4) {
                a0 = fma2(h2[q],     w2[q],     a0);
                a1 = fma2(h2[q + 1], w2[q + 1], a1);
                a2 = fma2(h2[q + 2], w2[q + 2], a2);
                a3 = fma2(h2[q + 3], w2[q + 3], a3);
            }
            a0 = fma2(h2[24], w2[24], a0);
            a0 = add2(a0, a1);
            a2 = add2(a2, a3);
            a0 = add2(a0, a2);
            const float2 s = u2f(a0);
            gates_s[g][v] = xp + s.x + s.y;
        }
        if (loader)
            asm volatile("cp.async.wait_group %0;" :: "n"(S_ - 3));
        asm volatile("bar.sync %0, 256;" :: "r"(g + 1) : "memory");

        // ---- phase 2: cell update(t) ----
        if (v < 50) {
            const float iv = gates_s[g][v];
            const float fv = gates_s[g][v + 50];
            const float gv = gates_s[g][v + 100];
            const float ov = gates_s[g][v + 150];
            const float si = sigm(iv);
            const float sf = sigm(fv);
            const float so = sigm(ov);
            const float tg = fmaf(2.f, sigm(2.f * gv), -1.f);
            c = fmaf(sf, c, si * tg);
            const float tc = fmaf(2.f, sigm(2.f * c), -1.f);
            const float hn = so * tc;
            h_s[g][v] = hn;
            g_hs[(size_t)(t * B_ + b) * 50 + v] = hn;
        }
        asm volatile("bar.sync %0, 256;" :: "r"(g + 1) : "memory");
    }
}

// ---------------------------------------------------------------------------
// K3: head. out[r,:] = relu(h_r @ W1^T + b1) @ W2^T + b2 (flat over 51200 rows)
// ---------------------------------------------------------------------------
__global__ __launch_bounds__(256) void k3_head(
    const float* __restrict__ W1, const float* __restrict__ b1,
    const float* __restrict__ W2, const float* __restrict__ b2,
    float* __restrict__ out)
{
    __shared__ float sW1[16 * 50];
    __shared__ float sW2[9 * 16];
    __shared__ float sb1[16];
    __shared__ float sb2[9];

    const int tid = threadIdx.x;
    for (int i = tid; i < 800; i += 256) sW1[i] = W1[i];
    if (tid < 144) sW2[tid] = W2[tid];
    if (tid < 16)  sb1[tid] = b1[tid];
    if (tid < 9)   sb2[tid] = b2[tid];
    __syncthreads();

    const int r = blockIdx.x * 256 + tid;
    const float* __restrict__ hrow = &g_hs[(size_t)r * 50];

    float hv[50];
#pragma unroll
    for (int k = 0; k < 50; k++) hv[k] = hrow[k];

    float z[16];
#pragma unroll
    for (int j = 0; j < 16; j++) {
        float a = sb1[j];
#pragma unroll
        for (int k = 0; k < 50; k++) a = fmaf(hv[k], sW1[j * 50 + k], a);
        z[j] = fmaxf(a, 0.f);
    }
#pragma unroll
    for (int p = 0; p < 9; p++) {
        float o = sb2[p];
#pragma unroll
        for (int j = 0; j < 16; j++) o = fmaf(z[j], sW2[p * 16 + j], o);
        out[r * 9 + p] = o;
    }
}

// ---------------------------------------------------------------------------
extern "C" void kernel_launch(void* const* d_in, const int* in_sizes, int n_in,
                              void* d_out, int out_size)
{
    const int*   tokens = (const int*)  d_in[0];
    const float* emb    = (const float*)d_in[1];
    const float* Wih    = (const float*)d_in[2];
    const float* Whh    = (const float*)d_in[3];
    const float* bih    = (const float*)d_in[4];
    const float* bhh    = (const float*)d_in[5];
    const float* W1     = (const float*)d_in[6];
    const float* b1     = (const float*)d_in[7];
    const float* W2     = (const float*)d_in[8];
    const float* b2     = (const float*)d_in[9];
    float* out = (float*)d_out;

    const int k1_smem = K1_SMEM_WORDS * 4;   // 168,736 B
    cudaFuncSetAttribute(k1_xproj, cudaFuncAttributeMaxDynamicSharedMemorySize,
                         k1_smem);

    k1_xproj<<<148, 512, k1_smem>>>(tokens, emb, Wih, bih, bhh);
    k2_lstm <<<B_ / 2, 512>>>(Whh);
    k3_head <<<M_ / 256, 256>>>(W1, b1, W2, b2, out);
}